// round 1
// baseline (speedup 1.0000x reference)
#include <cuda_runtime.h>
#include <math.h>

// Problem constants
#define CB   1024          // batch B (attention sequence length)
#define CN   14            // label nodes N
#define CIMG 512
#define CTXT 300
#define CD   812           // d_model
#define C3D  2436          // 3*D
#define CFF  2048
#define CHID 128
#define CT   (CB*CN)       // 14336 token rows

// ---------------- scratch (static device arrays; no allocation) ----------------
__device__ __align__(256) float d_A3[CB*C3D];                 // img @ Wimg^T       (1024 x 2436)
__device__ __align__(256) float d_Bn3[CN*C3D];                // wemb @ Wtxt^T + b  (14 x 2436)
__device__ __align__(256) float d_S0[CB*CB];                  // Aq @ Ak^T * scale  (1024 x 1024)
__device__ __align__(256) float d_wnm[CN*CB];                 // Bq @ Ak^T * scale  (14 x 1024)
__device__ __align__(256) float d_AvWo[CB*CD];                // Av @ Wo^T          (1024 x 812)
__device__ __align__(256) float d_BvWo[CN*CD];                // Bv @ Wo^T + bo     (14 x 812)
__device__ __align__(256) float d_P[(size_t)CN*CB*CB];        // attn               (14 x 1024 x 1024)
__device__ __align__(256) float d_projao[(size_t)CT*CD];      // out-proj(attn out) (14336 x 812)
__device__ __align__(256) float d_x1[(size_t)CT*CD];
__device__ __align__(256) float d_hff[(size_t)CT*CFF];
__device__ __align__(256) float d_ffo[(size_t)CT*CD];
__device__ __align__(256) float d_x2[(size_t)CT*CD];
__device__ __align__(256) float d_h1[(size_t)CT*CHID];
__device__ float d_Mmat[CN*CN];
__device__ float d_mvec[CN];

// ---------------- generic tiled SGEMM: C = alpha*A@op(B) + bias, opt relu -------
// NN: B is (K x N) row-major, element (k,j) at B[k*ldb + j]
// NT: B is (N x K) row-major, element (k,j) at B[j*ldb + k]
template<bool TRANSB, bool RELU>
__global__ __launch_bounds__(256)
void gemm_kernel(const float* __restrict__ A, const float* __restrict__ Bm,
                 float* __restrict__ C, const float* __restrict__ bias,
                 int M, int N, int K, int lda, int ldb, int ldc,
                 long long strideA, long long strideB, long long strideC, long long strideBias,
                 float alpha)
{
    __shared__ __align__(16) float As[16][128];
    __shared__ __align__(16) float Bs[16][128];

    const int z = blockIdx.z;
    const float* Ab = A + (size_t)z * strideA;
    const float* Bb = Bm + (size_t)z * strideB;
    float* Cb = C + (size_t)z * strideC;
    const float* biasb = bias ? (bias + (size_t)z * strideBias) : nullptr;

    const int i0 = blockIdx.y * 128;
    const int j0 = blockIdx.x * 128;
    const int tid = threadIdx.x;
    const int tx = tid & 15;
    const int ty = tid >> 4;

    float acc[8][8];
    #pragma unroll
    for (int r = 0; r < 8; r++)
        #pragma unroll
        for (int c = 0; c < 8; c++) acc[r][c] = 0.f;

    for (int k0 = 0; k0 < K; k0 += 16) {
        // ---- load A tile (128 rows x 16 k) via float4, store transposed ----
        #pragma unroll
        for (int s = 0; s < 2; s++) {
            int idx = tid + s * 256;
            int i = idx >> 2, kq = (idx & 3) * 4;
            int gi = i0 + i, gk = k0 + kq;
            float4 v = make_float4(0.f, 0.f, 0.f, 0.f);
            if (gi < M) {
                if (gk + 3 < K) {
                    v = *reinterpret_cast<const float4*>(Ab + (size_t)gi * lda + gk);
                } else {
                    float t0 = (gk + 0 < K) ? Ab[(size_t)gi * lda + gk + 0] : 0.f;
                    float t1 = (gk + 1 < K) ? Ab[(size_t)gi * lda + gk + 1] : 0.f;
                    float t2 = (gk + 2 < K) ? Ab[(size_t)gi * lda + gk + 2] : 0.f;
                    float t3 = (gk + 3 < K) ? Ab[(size_t)gi * lda + gk + 3] : 0.f;
                    v = make_float4(t0, t1, t2, t3);
                }
            }
            As[kq + 0][i] = v.x; As[kq + 1][i] = v.y; As[kq + 2][i] = v.z; As[kq + 3][i] = v.w;
        }
        // ---- load B tile ----
        if (TRANSB) {
            #pragma unroll
            for (int s = 0; s < 2; s++) {
                int idx = tid + s * 256;
                int j = idx >> 2, kq = (idx & 3) * 4;
                int gj = j0 + j, gk = k0 + kq;
                float4 v = make_float4(0.f, 0.f, 0.f, 0.f);
                if (gj < N) {
                    if (gk + 3 < K) {
                        v = *reinterpret_cast<const float4*>(Bb + (size_t)gj * ldb + gk);
                    } else {
                        float t0 = (gk + 0 < K) ? Bb[(size_t)gj * ldb + gk + 0] : 0.f;
                        float t1 = (gk + 1 < K) ? Bb[(size_t)gj * ldb + gk + 1] : 0.f;
                        float t2 = (gk + 2 < K) ? Bb[(size_t)gj * ldb + gk + 2] : 0.f;
                        float t3 = (gk + 3 < K) ? Bb[(size_t)gj * ldb + gk + 3] : 0.f;
                        v = make_float4(t0, t1, t2, t3);
                    }
                }
                Bs[kq + 0][j] = v.x; Bs[kq + 1][j] = v.y; Bs[kq + 2][j] = v.z; Bs[kq + 3][j] = v.w;
            }
        } else {
            #pragma unroll
            for (int s = 0; s < 2; s++) {
                int idx = tid + s * 256;
                int k = idx >> 5, jq = (idx & 31) * 4;
                int gk = k0 + k, gj = j0 + jq;
                float4 v = make_float4(0.f, 0.f, 0.f, 0.f);
                if (gk < K) {
                    if (gj + 3 < N) {
                        v = *reinterpret_cast<const float4*>(Bb + (size_t)gk * ldb + gj);
                    } else {
                        float t0 = (gj + 0 < N) ? Bb[(size_t)gk * ldb + gj + 0] : 0.f;
                        float t1 = (gj + 1 < N) ? Bb[(size_t)gk * ldb + gj + 1] : 0.f;
                        float t2 = (gj + 2 < N) ? Bb[(size_t)gk * ldb + gj + 2] : 0.f;
                        float t3 = (gj + 3 < N) ? Bb[(size_t)gk * ldb + gj + 3] : 0.f;
                        v = make_float4(t0, t1, t2, t3);
                    }
                }
                *reinterpret_cast<float4*>(&Bs[k][jq]) = v;
            }
        }
        __syncthreads();
        // ---- compute ----
        #pragma unroll
        for (int kk = 0; kk < 16; kk++) {
            float4 a0 = *reinterpret_cast<const float4*>(&As[kk][ty * 8]);
            float4 a1 = *reinterpret_cast<const float4*>(&As[kk][ty * 8 + 4]);
            float4 b0 = *reinterpret_cast<const float4*>(&Bs[kk][tx * 8]);
            float4 b1 = *reinterpret_cast<const float4*>(&Bs[kk][tx * 8 + 4]);
            float av[8] = {a0.x, a0.y, a0.z, a0.w, a1.x, a1.y, a1.z, a1.w};
            float bv[8] = {b0.x, b0.y, b0.z, b0.w, b1.x, b1.y, b1.z, b1.w};
            #pragma unroll
            for (int r = 0; r < 8; r++)
                #pragma unroll
                for (int c = 0; c < 8; c++)
                    acc[r][c] = fmaf(av[r], bv[c], acc[r][c]);
        }
        __syncthreads();
    }
    #pragma unroll
    for (int r = 0; r < 8; r++) {
        int gi = i0 + ty * 8 + r;
        if (gi >= M) break;
        float* crow = Cb + (size_t)gi * ldc;
        #pragma unroll
        for (int c = 0; c < 8; c++) {
            int gj = j0 + tx * 8 + c;
            if (gj >= N) break;
            float v = acc[r][c] * alpha;
            if (biasb) v += biasb[gj];
            if (RELU) v = fmaxf(v, 0.f);
            crow[gj] = v;
        }
    }
}

static inline void run_gemm(bool tb, bool relu, const float* A, const float* B, float* C,
                            const float* bias, int M, int N, int K, int lda, int ldb, int ldc,
                            long long sA, long long sB, long long sC, long long sBias,
                            float alpha, int batch)
{
    dim3 grid((N + 127) / 128, (M + 127) / 128, batch);
    if (tb) {
        if (relu) gemm_kernel<true, true><<<grid, 256>>>(A, B, C, bias, M, N, K, lda, ldb, ldc, sA, sB, sC, sBias, alpha);
        else      gemm_kernel<true, false><<<grid, 256>>>(A, B, C, bias, M, N, K, lda, ldb, ldc, sA, sB, sC, sBias, alpha);
    } else {
        if (relu) gemm_kernel<false, true><<<grid, 256>>>(A, B, C, bias, M, N, K, lda, ldb, ldc, sA, sB, sC, sBias, alpha);
        else      gemm_kernel<false, false><<<grid, 256>>>(A, B, C, bias, M, N, K, lda, ldb, ldc, sA, sB, sC, sBias, alpha);
    }
}

// ---------------- softmax over m: P[n,l,m] = softmax_m(S0[l,m] + w[n,m]) -------
__global__ __launch_bounds__(256)
void softmax_kernel(const float* __restrict__ S0, const float* __restrict__ w,
                    float* __restrict__ P)
{
    const int l = blockIdx.x, n = blockIdx.y, tid = threadIdx.x;
    const float* sr = S0 + (size_t)l * CB;
    const float* wr = w + (size_t)n * CB;
    float* pr = P + ((size_t)n * CB + l) * CB;

    __shared__ float red[8];
    __shared__ float bcast;

    float vals[4];
    float mx = -1e30f;
    #pragma unroll
    for (int s = 0; s < 4; s++) {
        int m = tid + s * 256;
        float v = sr[m] + wr[m];
        vals[s] = v;
        mx = fmaxf(mx, v);
    }
    #pragma unroll
    for (int o = 16; o > 0; o >>= 1) mx = fmaxf(mx, __shfl_down_sync(0xffffffffu, mx, o));
    if ((tid & 31) == 0) red[tid >> 5] = mx;
    __syncthreads();
    if (tid == 0) {
        float m2 = -1e30f;
        for (int i = 0; i < 8; i++) m2 = fmaxf(m2, red[i]);
        bcast = m2;
    }
    __syncthreads();
    mx = bcast;
    float sum = 0.f;
    #pragma unroll
    for (int s = 0; s < 4; s++) { vals[s] = __expf(vals[s] - mx); sum += vals[s]; }
    #pragma unroll
    for (int o = 16; o > 0; o >>= 1) sum += __shfl_down_sync(0xffffffffu, sum, o);
    __syncthreads();
    if ((tid & 31) == 0) red[tid >> 5] = sum;
    __syncthreads();
    if (tid == 0) {
        float s2 = 0.f;
        for (int i = 0; i < 8; i++) s2 += red[i];
        bcast = 1.0f / s2;
    }
    __syncthreads();
    float inv = bcast;
    #pragma unroll
    for (int s = 0; s < 4; s++) pr[tid + s * 256] = vals[s] * inv;
}

// ---------------- LayerNorm kernels (one block per row of 812) -----------------
__global__ __launch_bounds__(256)
void ln1_kernel(const float* __restrict__ img, const float* __restrict__ wemb,
                const float* __restrict__ res, const float* __restrict__ g,
                const float* __restrict__ be, float* __restrict__ out)
{
    __shared__ float row[CD];
    __shared__ float red[8];
    __shared__ float sMean, sRstd;
    const int t = blockIdx.x;
    const int b = t / CN;
    const int n = t - b * CN;
    const int tid = threadIdx.x;
    const float* resr = res + (size_t)t * CD;

    float partial = 0.f;
    for (int j = tid; j < CD; j += 256) {
        float v = ((j < CIMG) ? img[(size_t)b * CIMG + j] : wemb[(size_t)n * CTXT + (j - CIMG)]) + resr[j];
        row[j] = v;
        partial += v;
    }
    #pragma unroll
    for (int o = 16; o > 0; o >>= 1) partial += __shfl_down_sync(0xffffffffu, partial, o);
    if ((tid & 31) == 0) red[tid >> 5] = partial;
    __syncthreads();
    if (tid == 0) { float s = 0.f; for (int i = 0; i < 8; i++) s += red[i]; sMean = s / CD; }
    __syncthreads();
    float mu = sMean;
    float p2 = 0.f;
    for (int j = tid; j < CD; j += 256) { float d = row[j] - mu; p2 += d * d; }
    #pragma unroll
    for (int o = 16; o > 0; o >>= 1) p2 += __shfl_down_sync(0xffffffffu, p2, o);
    __syncthreads();
    if ((tid & 31) == 0) red[tid >> 5] = p2;
    __syncthreads();
    if (tid == 0) { float s = 0.f; for (int i = 0; i < 8; i++) s += red[i]; sRstd = rsqrtf(s / CD + 1e-5f); }
    __syncthreads();
    float rs = sRstd;
    float* o = out + (size_t)t * CD;
    for (int j = tid; j < CD; j += 256) o[j] = (row[j] - mu) * rs * g[j] + be[j];
}

__global__ __launch_bounds__(256)
void ln2_kernel(const float* __restrict__ x1, const float* __restrict__ ff,
                const float* __restrict__ g, const float* __restrict__ be,
                float* __restrict__ out)
{
    __shared__ float row[CD];
    __shared__ float red[8];
    __shared__ float sMean, sRstd;
    const int t = blockIdx.x;
    const int tid = threadIdx.x;
    const float* x1r = x1 + (size_t)t * CD;
    const float* ffr = ff + (size_t)t * CD;

    float partial = 0.f;
    for (int j = tid; j < CD; j += 256) {
        float v = x1r[j] + ffr[j];
        row[j] = v;
        partial += v;
    }
    #pragma unroll
    for (int o = 16; o > 0; o >>= 1) partial += __shfl_down_sync(0xffffffffu, partial, o);
    if ((tid & 31) == 0) red[tid >> 5] = partial;
    __syncthreads();
    if (tid == 0) { float s = 0.f; for (int i = 0; i < 8; i++) s += red[i]; sMean = s / CD; }
    __syncthreads();
    float mu = sMean;
    float p2 = 0.f;
    for (int j = tid; j < CD; j += 256) { float d = row[j] - mu; p2 += d * d; }
    #pragma unroll
    for (int o = 16; o > 0; o >>= 1) p2 += __shfl_down_sync(0xffffffffu, p2, o);
    __syncthreads();
    if ((tid & 31) == 0) red[tid >> 5] = p2;
    __syncthreads();
    if (tid == 0) { float s = 0.f; for (int i = 0; i < 8; i++) s += red[i]; sRstd = rsqrtf(s / CD + 1e-5f); }
    __syncthreads();
    float rs = sRstd;
    float* o = out + (size_t)t * CD;
    for (int j = tid; j < CD; j += 256) o[j] = (row[j] - mu) * rs * g[j] + be[j];
}

// ---------------- GCN: dense 14x14 normalized adjacency + mean vector ----------
__global__ void gcn_prep_kernel(const int* __restrict__ eidx, int E,
                                float* __restrict__ Mout, float* __restrict__ mvec)
{
    __shared__ float deg[CN];
    __shared__ float dinv[CN];
    __shared__ float Msh[CN * CN];
    const int tid = threadIdx.x;
    if (tid < CN) deg[tid] = 1.0f;  // self loop
    for (int i = tid; i < CN * CN; i += blockDim.x) Msh[i] = 0.f;
    __syncthreads();
    for (int e = tid; e < E; e += blockDim.x) atomicAdd(&deg[eidx[E + e]], 1.0f);
    __syncthreads();
    if (tid < CN) dinv[tid] = rsqrtf(deg[tid]);
    __syncthreads();
    for (int e = tid; e < E; e += blockDim.x) {
        int s = eidx[e], d = eidx[E + e];
        atomicAdd(&Msh[d * CN + s], dinv[s] * dinv[d]);
    }
    if (tid < CN) atomicAdd(&Msh[tid * CN + tid], dinv[tid] * dinv[tid]);
    __syncthreads();
    for (int i = tid; i < CN * CN; i += blockDim.x) Mout[i] = Msh[i];
    if (tid < CN) {
        float sum = 0.f;
        for (int d = 0; d < CN; d++) sum += Msh[d * CN + tid];
        mvec[tid] = sum * (1.0f / CN);
    }
}

// ---- fused: gcn1-aggregate+relu, mvec-weighted sum, gcn2, relu, linear head ---
__global__ __launch_bounds__(128)
void gcn_final_kernel(const float* __restrict__ h1, const float* __restrict__ Mmat,
                      const float* __restrict__ mvec, const float* __restrict__ gb1,
                      const float* __restrict__ W2, const float* __restrict__ gb2,
                      const float* __restrict__ linW, const float* __restrict__ linb,
                      float* __restrict__ out)
{
    const int b = blockIdx.x, f = threadIdx.x;
    __shared__ float sh_h[CN][CHID];
    __shared__ float sh_M[CN * CN];
    __shared__ float sh_mv[CN];
    __shared__ float zsh[CHID];
    __shared__ float rsh[CHID];

    for (int s = 0; s < CN; s++)
        sh_h[s][f] = h1[((size_t)b * CN + s) * CHID + f];
    for (int i = f; i < CN * CN; i += CHID) sh_M[i] = Mmat[i];
    if (f < CN) sh_mv[f] = mvec[f];
    __syncthreads();

    const float bf = gb1[f];
    float z = 0.f;
    #pragma unroll
    for (int d = 0; d < CN; d++) {
        float acc = bf;
        #pragma unroll
        for (int s = 0; s < CN; s++) acc += sh_M[d * CN + s] * sh_h[s][f];
        z += sh_mv[d] * fmaxf(acc, 0.f);
    }
    zsh[f] = z;
    __syncthreads();

    float t = gb2[f];
    for (int g = 0; g < CHID; g++) t += zsh[g] * W2[g * CHID + f];
    rsh[f] = fmaxf(t, 0.f);
    __syncthreads();

    if (f < CN) {
        float o = linb[f];
        for (int g = 0; g < CHID; g++) o += rsh[g] * linW[g * CN + f];
        out[(size_t)b * CN + f] = o;
    }
}

// --------------------------------- launch --------------------------------------
extern "C" void kernel_launch(void* const* d_in, const int* in_sizes, int n_in,
                              void* d_out, int out_size)
{
    (void)n_in; (void)out_size;
    const float* img   = (const float*)d_in[0];
    const float* wemb  = (const float*)d_in[1];
    const int*   eidx  = (const int*)  d_in[2];
    const float* Wqkv  = (const float*)d_in[3];
    const float* bqkv  = (const float*)d_in[4];
    const float* Wo    = (const float*)d_in[5];
    const float* bo    = (const float*)d_in[6];
    const float* ln1g  = (const float*)d_in[7];
    const float* ln1b  = (const float*)d_in[8];
    const float* ln2g  = (const float*)d_in[9];
    const float* ln2b  = (const float*)d_in[10];
    const float* W1    = (const float*)d_in[11];
    const float* b1    = (const float*)d_in[12];
    const float* W2f   = (const float*)d_in[13];
    const float* b2    = (const float*)d_in[14];
    const float* g1w   = (const float*)d_in[15];
    const float* g1b   = (const float*)d_in[16];
    const float* g2w   = (const float*)d_in[17];
    const float* g2b   = (const float*)d_in[18];
    const float* linw  = (const float*)d_in[19];
    const float* linb  = (const float*)d_in[20];
    float* out = (float*)d_out;
    const int E = in_sizes[2] / 2;

    float *A3, *Bn3, *S0, *wnm, *AvWo, *BvWo, *P, *projao, *x1, *hff, *ffo, *x2, *h1, *Mm, *mv;
    cudaGetSymbolAddress((void**)&A3,     d_A3);
    cudaGetSymbolAddress((void**)&Bn3,    d_Bn3);
    cudaGetSymbolAddress((void**)&S0,     d_S0);
    cudaGetSymbolAddress((void**)&wnm,    d_wnm);
    cudaGetSymbolAddress((void**)&AvWo,   d_AvWo);
    cudaGetSymbolAddress((void**)&BvWo,   d_BvWo);
    cudaGetSymbolAddress((void**)&P,      d_P);
    cudaGetSymbolAddress((void**)&projao, d_projao);
    cudaGetSymbolAddress((void**)&x1,     d_x1);
    cudaGetSymbolAddress((void**)&hff,    d_hff);
    cudaGetSymbolAddress((void**)&ffo,    d_ffo);
    cudaGetSymbolAddress((void**)&x2,     d_x2);
    cudaGetSymbolAddress((void**)&h1,     d_h1);
    cudaGetSymbolAddress((void**)&Mm,     d_Mmat);
    cudaGetSymbolAddress((void**)&mv,     d_mvec);

    const float scale = 1.0f / sqrtf((float)CD);

    // QKV rank-separation: qkv[b,n] = A3[b] + Bn3[n]
    run_gemm(true,  false, img,  Wqkv,        A3,  nullptr, CB, C3D, CIMG, CIMG, CD, C3D, 0, 0, 0, 0, 1.f, 1);
    run_gemm(true,  false, wemb, Wqkv + CIMG, Bn3, bqkv,    CN, C3D, CTXT, CTXT, CD, C3D, 0, 0, 0, 0, 1.f, 1);

    // Score pieces (softmax-invariant terms dropped)
    run_gemm(true,  false, A3,            A3 + CD, S0,  nullptr, CB, CB, CD, C3D, C3D, CB, 0, 0, 0, 0, scale, 1);
    run_gemm(true,  false, Bn3,           A3 + CD, wnm, nullptr, CN, CB, CD, C3D, C3D, CB, 0, 0, 0, 0, scale, 1);

    // Fold out-projection into V
    run_gemm(true,  false, A3 + 2 * CD,  Wo, AvWo, nullptr, CB, CD, CD, C3D, CD, CD, 0, 0, 0, 0, 1.f, 1);
    run_gemm(true,  false, Bn3 + 2 * CD, Wo, BvWo, bo,      CN, CD, CD, C3D, CD, CD, 0, 0, 0, 0, 1.f, 1);

    // Softmax per (n,l) row
    softmax_kernel<<<dim3(CB, CN), 256>>>(S0, wnm, P);

    // projao[l,n,:] = P_n[l,:] @ AvWo + BvWo[n]   (batched over n)
    run_gemm(false, false, P, AvWo, projao, BvWo, CB, CD, CB, CB, CD, CN * CD,
             (long long)CB * CB, 0, CD, CD, 1.f, CN);

    // x1 = LN(node + projao)
    ln1_kernel<<<CT, 256>>>(img, wemb, projao, ln1g, ln1b, x1);

    // FFN
    run_gemm(false, true,  x1,  W1,  hff, b1, CT, CFF, CD,  CD,  CFF, CFF, 0, 0, 0, 0, 1.f, 1);
    run_gemm(false, false, hff, W2f, ffo, b2, CT, CD,  CFF, CFF, CD,  CD,  0, 0, 0, 0, 1.f, 1);

    // x2 = LN(x1 + ffn)
    ln2_kernel<<<CT, 256>>>(x1, ffo, ln2g, ln2b, x2);

    // GCN feature transform (big part): h1 = x2 @ gcn1_w
    run_gemm(false, false, x2, g1w, h1, nullptr, CT, CHID, CD, CD, CHID, CHID, 0, 0, 0, 0, 1.f, 1);

    // Dense adjacency + fused tail
    gcn_prep_kernel<<<1, 256>>>(eidx, E, Mm, mv);
    gcn_final_kernel<<<CB, 128>>>(h1, Mm, mv, g1b, g2w, g2b, linw, linb, out);
}

// round 2
// speedup vs baseline: 1.0036x; 1.0036x over previous
#include <cuda_runtime.h>
#include <math.h>

// Problem constants
#define CB   1024          // batch B (attention sequence length)
#define CN   14            // label nodes N
#define CIMG 512
#define CTXT 300
#define CD   812           // d_model
#define C3D  2436          // 3*D
#define CFF  2048
#define CHID 128
#define CT   (CB*CN)       // 14336 token rows

// ---------------- scratch (static device arrays; no allocation) ----------------
__device__ __align__(256) float d_A3[CB*C3D];                 // img @ Wimg^T       (1024 x 2436)
__device__ __align__(256) float d_Bn3[CN*C3D];                // wemb @ Wtxt^T + b  (14 x 2436)
__device__ __align__(256) float d_S0[CB*CB];                  // Aq @ Ak^T * scale  (1024 x 1024)
__device__ __align__(256) float d_wnm[CN*CB];                 // Bq @ Ak^T * scale  (14 x 1024)
__device__ __align__(256) float d_AvWo[CB*CD];                // Av @ Wo^T          (1024 x 812)
__device__ __align__(256) float d_BvWo[CN*CD];                // Bv @ Wo^T + bo     (14 x 812)
__device__ __align__(256) float d_P[(size_t)CN*CB*CB];        // attn               (14 x 1024 x 1024)
__device__ __align__(256) float d_projao[(size_t)CT*CD];      // out-proj(attn out) (14336 x 812)
__device__ __align__(256) float d_x1[(size_t)CT*CD];
__device__ __align__(256) float d_hff[(size_t)CT*CFF];
__device__ __align__(256) float d_ffo[(size_t)CT*CD];
__device__ __align__(256) float d_x2[(size_t)CT*CD];
__device__ __align__(256) float d_h1[(size_t)CT*CHID];
__device__ float d_Mmat[CN*CN];
__device__ float d_mvec[CN];

// ---------------- packed f32x2 FMA (FFMA2; only reachable via PTX) -------------
__device__ __forceinline__ unsigned long long fma2(unsigned long long a,
                                                   unsigned long long b,
                                                   unsigned long long c)
{
    unsigned long long d;
    asm("fma.rn.f32x2 %0, %1, %2, %3;" : "=l"(d) : "l"(a), "l"(b), "l"(c));
    return d;
}
union F4U2 { float4 f4; unsigned long long u[2]; float f[4]; };

// ---------------- generic tiled SGEMM: C = alpha*A@op(B) + bias, opt relu -------
// NN: B is (K x N) row-major, element (k,j) at B[k*ldb + j]
// NT: B is (N x K) row-major, element (k,j) at B[j*ldb + k]
// Inner product uses FFMA2 over column pairs; A is stored lane-duplicated in
// shared so the scalar A operand needs no per-k packing MOVs.
template<bool TRANSB, bool RELU>
__global__ __launch_bounds__(256)
void gemm_kernel(const float* __restrict__ A, const float* __restrict__ Bm,
                 float* __restrict__ C, const float* __restrict__ bias,
                 int M, int N, int K, int lda, int ldb, int ldc,
                 long long strideA, long long strideB, long long strideC, long long strideBias,
                 float alpha)
{
    __shared__ __align__(16) float As[16][256];   // [k][2*i] duplicated pairs
    __shared__ __align__(16) float Bs[16][128];   // [k][j]

    const int z = blockIdx.z;
    const float* Ab = A + (size_t)z * strideA;
    const float* Bb = Bm + (size_t)z * strideB;
    float* Cb = C + (size_t)z * strideC;
    const float* biasb = bias ? (bias + (size_t)z * strideBias) : nullptr;

    const int i0 = blockIdx.y * 128;
    const int j0 = blockIdx.x * 128;
    const int tid = threadIdx.x;
    const int tx = tid & 15;
    const int ty = tid >> 4;

    unsigned long long acc2[8][4];
    #pragma unroll
    for (int r = 0; r < 8; r++)
        #pragma unroll
        for (int c = 0; c < 4; c++) acc2[r][c] = 0ULL;

    for (int k0 = 0; k0 < K; k0 += 16) {
        // ---- load A tile (128 rows x 16 k), store k-major with lane-dup ----
        #pragma unroll
        for (int s = 0; s < 2; s++) {
            int idx = tid + s * 256;
            int i = idx >> 2, kq = (idx & 3) * 4;
            int gi = i0 + i, gk = k0 + kq;
            float4 v = make_float4(0.f, 0.f, 0.f, 0.f);
            if (gi < M) {
                if (gk + 3 < K) {
                    v = *reinterpret_cast<const float4*>(Ab + (size_t)gi * lda + gk);
                } else {
                    float t0 = (gk + 0 < K) ? Ab[(size_t)gi * lda + gk + 0] : 0.f;
                    float t1 = (gk + 1 < K) ? Ab[(size_t)gi * lda + gk + 1] : 0.f;
                    float t2 = (gk + 2 < K) ? Ab[(size_t)gi * lda + gk + 2] : 0.f;
                    float t3 = (gk + 3 < K) ? Ab[(size_t)gi * lda + gk + 3] : 0.f;
                    v = make_float4(t0, t1, t2, t3);
                }
            }
            *reinterpret_cast<float2*>(&As[kq + 0][2 * i]) = make_float2(v.x, v.x);
            *reinterpret_cast<float2*>(&As[kq + 1][2 * i]) = make_float2(v.y, v.y);
            *reinterpret_cast<float2*>(&As[kq + 2][2 * i]) = make_float2(v.z, v.z);
            *reinterpret_cast<float2*>(&As[kq + 3][2 * i]) = make_float2(v.w, v.w);
        }
        // ---- load B tile ----
        if (TRANSB) {
            #pragma unroll
            for (int s = 0; s < 2; s++) {
                int idx = tid + s * 256;
                int j = idx >> 2, kq = (idx & 3) * 4;
                int gj = j0 + j, gk = k0 + kq;
                float4 v = make_float4(0.f, 0.f, 0.f, 0.f);
                if (gj < N) {
                    if (gk + 3 < K) {
                        v = *reinterpret_cast<const float4*>(Bb + (size_t)gj * ldb + gk);
                    } else {
                        float t0 = (gk + 0 < K) ? Bb[(size_t)gj * ldb + gk + 0] : 0.f;
                        float t1 = (gk + 1 < K) ? Bb[(size_t)gj * ldb + gk + 1] : 0.f;
                        float t2 = (gk + 2 < K) ? Bb[(size_t)gj * ldb + gk + 2] : 0.f;
                        float t3 = (gk + 3 < K) ? Bb[(size_t)gj * ldb + gk + 3] : 0.f;
                        v = make_float4(t0, t1, t2, t3);
                    }
                }
                Bs[kq + 0][j] = v.x; Bs[kq + 1][j] = v.y; Bs[kq + 2][j] = v.z; Bs[kq + 3][j] = v.w;
            }
        } else {
            #pragma unroll
            for (int s = 0; s < 2; s++) {
                int idx = tid + s * 256;
                int k = idx >> 5, jq = (idx & 31) * 4;
                int gk = k0 + k, gj = j0 + jq;
                float4 v = make_float4(0.f, 0.f, 0.f, 0.f);
                if (gk < K) {
                    if (gj + 3 < N) {
                        v = *reinterpret_cast<const float4*>(Bb + (size_t)gk * ldb + gj);
                    } else {
                        float t0 = (gj + 0 < N) ? Bb[(size_t)gk * ldb + gj + 0] : 0.f;
                        float t1 = (gj + 1 < N) ? Bb[(size_t)gk * ldb + gj + 1] : 0.f;
                        float t2 = (gj + 2 < N) ? Bb[(size_t)gk * ldb + gj + 2] : 0.f;
                        float t3 = (gj + 3 < N) ? Bb[(size_t)gk * ldb + gj + 3] : 0.f;
                        v = make_float4(t0, t1, t2, t3);
                    }
                }
                *reinterpret_cast<float4*>(&Bs[k][jq]) = v;
            }
        }
        __syncthreads();
        // ---- compute (FFMA2 over column pairs) ----
        #pragma unroll
        for (int kk = 0; kk < 16; kk++) {
            F4U2 a0, a1, a2, a3, b0, b1;
            a0.f4 = *reinterpret_cast<const float4*>(&As[kk][ty * 16 + 0]);
            a1.f4 = *reinterpret_cast<const float4*>(&As[kk][ty * 16 + 4]);
            a2.f4 = *reinterpret_cast<const float4*>(&As[kk][ty * 16 + 8]);
            a3.f4 = *reinterpret_cast<const float4*>(&As[kk][ty * 16 + 12]);
            b0.f4 = *reinterpret_cast<const float4*>(&Bs[kk][tx * 8]);
            b1.f4 = *reinterpret_cast<const float4*>(&Bs[kk][tx * 8 + 4]);
            unsigned long long ap[8] = {a0.u[0], a0.u[1], a1.u[0], a1.u[1],
                                        a2.u[0], a2.u[1], a3.u[0], a3.u[1]};
            unsigned long long bp[4] = {b0.u[0], b0.u[1], b1.u[0], b1.u[1]};
            #pragma unroll
            for (int r = 0; r < 8; r++)
                #pragma unroll
                for (int c = 0; c < 4; c++)
                    acc2[r][c] = fma2(ap[r], bp[c], acc2[r][c]);
        }
        __syncthreads();
    }
    #pragma unroll
    for (int r = 0; r < 8; r++) {
        int gi = i0 + ty * 8 + r;
        if (gi >= M) break;
        float* crow = Cb + (size_t)gi * ldc;
        #pragma unroll
        for (int c = 0; c < 4; c++) {
            F4U2 p; p.u[0] = acc2[r][c]; // (col 2c, col 2c+1)
            #pragma unroll
            for (int h = 0; h < 2; h++) {
                int gj = j0 + tx * 8 + c * 2 + h;
                if (gj < N) {
                    float v = p.f[h] * alpha;
                    if (biasb) v += biasb[gj];
                    if (RELU) v = fmaxf(v, 0.f);
                    crow[gj] = v;
                }
            }
        }
    }
}

static inline void run_gemm(bool tb, bool relu, const float* A, const float* B, float* C,
                            const float* bias, int M, int N, int K, int lda, int ldb, int ldc,
                            long long sA, long long sB, long long sC, long long sBias,
                            float alpha, int batch)
{
    dim3 grid((N + 127) / 128, (M + 127) / 128, batch);
    if (tb) {
        if (relu) gemm_kernel<true, true><<<grid, 256>>>(A, B, C, bias, M, N, K, lda, ldb, ldc, sA, sB, sC, sBias, alpha);
        else      gemm_kernel<true, false><<<grid, 256>>>(A, B, C, bias, M, N, K, lda, ldb, ldc, sA, sB, sC, sBias, alpha);
    } else {
        if (relu) gemm_kernel<false, true><<<grid, 256>>>(A, B, C, bias, M, N, K, lda, ldb, ldc, sA, sB, sC, sBias, alpha);
        else      gemm_kernel<false, false><<<grid, 256>>>(A, B, C, bias, M, N, K, lda, ldb, ldc, sA, sB, sC, sBias, alpha);
    }
}

// ------------- small-M (M==14) NT GEMM: C[14,N] = alpha*A@B^T + bias -----------
// A: (14 x K) row-major cached in smem.  B: (N x K) row-major.
// 8 threads cooperate per output column (split-K + shfl reduce).
__global__ __launch_bounds__(256)
void small_nt_kernel(const float* __restrict__ A, const float* __restrict__ Bm,
                     float* __restrict__ C, const float* __restrict__ bias,
                     int N, int K, int lda, int ldb, int ldc, float alpha)
{
    __shared__ float sA[CN * 812];   // K <= 812
    const int tid = threadIdx.x;
    const int col = blockIdx.x * 32 + (tid >> 3);
    const int sub = tid & 7;

    // cooperative load of A into smem (rows packed at stride K)
    for (int idx = tid; idx < CN * (K >> 2); idx += 256) {
        int m = idx / (K >> 2);
        int kq = (idx - m * (K >> 2)) * 4;
        *reinterpret_cast<float4*>(&sA[m * K + kq]) =
            *reinterpret_cast<const float4*>(A + (size_t)m * lda + kq);
    }
    __syncthreads();

    float acc[CN];
    #pragma unroll
    for (int m = 0; m < CN; m++) acc[m] = 0.f;

    if (col < N) {
        const int Kc = ((K / 8 + 3) & ~3);          // 4-aligned chunk
        int ks = sub * Kc;
        int ke = min(K, ks + Kc);
        const float* Brow = Bm + (size_t)col * ldb;
        for (int k = ks; k < ke; k += 4) {
            float4 b = *reinterpret_cast<const float4*>(Brow + k);
            #pragma unroll
            for (int m = 0; m < CN; m++) {
                const float* ar = &sA[m * K + k];
                acc[m] = fmaf(ar[0], b.x, acc[m]);
                acc[m] = fmaf(ar[1], b.y, acc[m]);
                acc[m] = fmaf(ar[2], b.z, acc[m]);
                acc[m] = fmaf(ar[3], b.w, acc[m]);
            }
        }
    }
    // reduce across the 8 sub-threads
    #pragma unroll
    for (int off = 4; off > 0; off >>= 1)
        #pragma unroll
        for (int m = 0; m < CN; m++)
            acc[m] += __shfl_down_sync(0xffffffffu, acc[m], off, 8);

    if (sub == 0 && col < N) {
        float bv = bias ? bias[col] : 0.f;
        #pragma unroll
        for (int m = 0; m < CN; m++)
            C[(size_t)m * ldc + col] = acc[m] * alpha + bv;
    }
}

// ---------------- softmax over m: P[n,l,m] = softmax_m(S0[l,m] + w[n,m]) -------
__global__ __launch_bounds__(256)
void softmax_kernel(const float* __restrict__ S0, const float* __restrict__ w,
                    float* __restrict__ P)
{
    const int l = blockIdx.x, n = blockIdx.y, tid = threadIdx.x;
    const float* sr = S0 + (size_t)l * CB;
    const float* wr = w + (size_t)n * CB;
    float* pr = P + ((size_t)n * CB + l) * CB;

    __shared__ float red[8];
    __shared__ float bcast;

    float vals[4];
    float mx = -1e30f;
    #pragma unroll
    for (int s = 0; s < 4; s++) {
        int m = tid + s * 256;
        float v = sr[m] + wr[m];
        vals[s] = v;
        mx = fmaxf(mx, v);
    }
    #pragma unroll
    for (int o = 16; o > 0; o >>= 1) mx = fmaxf(mx, __shfl_down_sync(0xffffffffu, mx, o));
    if ((tid & 31) == 0) red[tid >> 5] = mx;
    __syncthreads();
    if (tid == 0) {
        float m2 = -1e30f;
        for (int i = 0; i < 8; i++) m2 = fmaxf(m2, red[i]);
        bcast = m2;
    }
    __syncthreads();
    mx = bcast;
    float sum = 0.f;
    #pragma unroll
    for (int s = 0; s < 4; s++) { vals[s] = __expf(vals[s] - mx); sum += vals[s]; }
    #pragma unroll
    for (int o = 16; o > 0; o >>= 1) sum += __shfl_down_sync(0xffffffffu, sum, o);
    __syncthreads();
    if ((tid & 31) == 0) red[tid >> 5] = sum;
    __syncthreads();
    if (tid == 0) {
        float s2 = 0.f;
        for (int i = 0; i < 8; i++) s2 += red[i];
        bcast = 1.0f / s2;
    }
    __syncthreads();
    float inv = bcast;
    #pragma unroll
    for (int s = 0; s < 4; s++) pr[tid + s * 256] = vals[s] * inv;
}

// ---------------- LayerNorm kernels (one block per row of 812) -----------------
__global__ __launch_bounds__(256)
void ln1_kernel(const float* __restrict__ img, const float* __restrict__ wemb,
                const float* __restrict__ res, const float* __restrict__ g,
                const float* __restrict__ be, float* __restrict__ out)
{
    __shared__ float row[CD];
    __shared__ float red[8];
    __shared__ float sMean, sRstd;
    const int t = blockIdx.x;
    const int b = t / CN;
    const int n = t - b * CN;
    const int tid = threadIdx.x;
    const float* resr = res + (size_t)t * CD;

    float partial = 0.f;
    for (int j = tid; j < CD; j += 256) {
        float v = ((j < CIMG) ? img[(size_t)b * CIMG + j] : wemb[(size_t)n * CTXT + (j - CIMG)]) + resr[j];
        row[j] = v;
        partial += v;
    }
    #pragma unroll
    for (int o = 16; o > 0; o >>= 1) partial += __shfl_down_sync(0xffffffffu, partial, o);
    if ((tid & 31) == 0) red[tid >> 5] = partial;
    __syncthreads();
    if (tid == 0) { float s = 0.f; for (int i = 0; i < 8; i++) s += red[i]; sMean = s / CD; }
    __syncthreads();
    float mu = sMean;
    float p2 = 0.f;
    for (int j = tid; j < CD; j += 256) { float d = row[j] - mu; p2 += d * d; }
    #pragma unroll
    for (int o = 16; o > 0; o >>= 1) p2 += __shfl_down_sync(0xffffffffu, p2, o);
    __syncthreads();
    if ((tid & 31) == 0) red[tid >> 5] = p2;
    __syncthreads();
    if (tid == 0) { float s = 0.f; for (int i = 0; i < 8; i++) s += red[i]; sRstd = rsqrtf(s / CD + 1e-5f); }
    __syncthreads();
    float rs = sRstd;
    float* o = out + (size_t)t * CD;
    for (int j = tid; j < CD; j += 256) o[j] = (row[j] - mu) * rs * g[j] + be[j];
}

__global__ __launch_bounds__(256)
void ln2_kernel(const float* __restrict__ x1, const float* __restrict__ ff,
                const float* __restrict__ g, const float* __restrict__ be,
                float* __restrict__ out)
{
    __shared__ float row[CD];
    __shared__ float red[8];
    __shared__ float sMean, sRstd;
    const int t = blockIdx.x;
    const int tid = threadIdx.x;
    const float* x1r = x1 + (size_t)t * CD;
    const float* ffr = ff + (size_t)t * CD;

    float partial = 0.f;
    for (int j = tid; j < CD; j += 256) {
        float v = x1r[j] + ffr[j];
        row[j] = v;
        partial += v;
    }
    #pragma unroll
    for (int o = 16; o > 0; o >>= 1) partial += __shfl_down_sync(0xffffffffu, partial, o);
    if ((tid & 31) == 0) red[tid >> 5] = partial;
    __syncthreads();
    if (tid == 0) { float s = 0.f; for (int i = 0; i < 8; i++) s += red[i]; sMean = s / CD; }
    __syncthreads();
    float mu = sMean;
    float p2 = 0.f;
    for (int j = tid; j < CD; j += 256) { float d = row[j] - mu; p2 += d * d; }
    #pragma unroll
    for (int o = 16; o > 0; o >>= 1) p2 += __shfl_down_sync(0xffffffffu, p2, o);
    __syncthreads();
    if ((tid & 31) == 0) red[tid >> 5] = p2;
    __syncthreads();
    if (tid == 0) { float s = 0.f; for (int i = 0; i < 8; i++) s += red[i]; sRstd = rsqrtf(s / CD + 1e-5f); }
    __syncthreads();
    float rs = sRstd;
    float* o = out + (size_t)t * CD;
    for (int j = tid; j < CD; j += 256) o[j] = (row[j] - mu) * rs * g[j] + be[j];
}

// ---------------- GCN: dense 14x14 normalized adjacency + mean vector ----------
__global__ void gcn_prep_kernel(const int* __restrict__ eidx, int E,
                                float* __restrict__ Mout, float* __restrict__ mvec)
{
    __shared__ float deg[CN];
    __shared__ float dinv[CN];
    __shared__ float Msh[CN * CN];
    const int tid = threadIdx.x;
    if (tid < CN) deg[tid] = 1.0f;  // self loop
    for (int i = tid; i < CN * CN; i += blockDim.x) Msh[i] = 0.f;
    __syncthreads();
    for (int e = tid; e < E; e += blockDim.x) atomicAdd(&deg[eidx[E + e]], 1.0f);
    __syncthreads();
    if (tid < CN) dinv[tid] = rsqrtf(deg[tid]);
    __syncthreads();
    for (int e = tid; e < E; e += blockDim.x) {
        int s = eidx[e], d = eidx[E + e];
        atomicAdd(&Msh[d * CN + s], dinv[s] * dinv[d]);
    }
    if (tid < CN) atomicAdd(&Msh[tid * CN + tid], dinv[tid] * dinv[tid]);
    __syncthreads();
    for (int i = tid; i < CN * CN; i += blockDim.x) Mout[i] = Msh[i];
    if (tid < CN) {
        float sum = 0.f;
        for (int d = 0; d < CN; d++) sum += Msh[d * CN + tid];
        mvec[tid] = sum * (1.0f / CN);
    }
}

// ---- fused: gcn1-aggregate+relu, mvec-weighted sum, gcn2, relu, linear head ---
__global__ __launch_bounds__(128)
void gcn_final_kernel(const float* __restrict__ h1, const float* __restrict__ Mmat,
                      const float* __restrict__ mvec, const float* __restrict__ gb1,
                      const float* __restrict__ W2, const float* __restrict__ gb2,
                      const float* __restrict__ linW, const float* __restrict__ linb,
                      float* __restrict__ out)
{
    const int b = blockIdx.x, f = threadIdx.x;
    __shared__ float sh_h[CN][CHID];
    __shared__ float sh_M[CN * CN];
    __shared__ float sh_mv[CN];
    __shared__ float zsh[CHID];
    __shared__ float rsh[CHID];

    for (int s = 0; s < CN; s++)
        sh_h[s][f] = h1[((size_t)b * CN + s) * CHID + f];
    for (int i = f; i < CN * CN; i += CHID) sh_M[i] = Mmat[i];
    if (f < CN) sh_mv[f] = mvec[f];
    __syncthreads();

    const float bf = gb1[f];
    float z = 0.f;
    #pragma unroll
    for (int d = 0; d < CN; d++) {
        float acc = bf;
        #pragma unroll
        for (int s = 0; s < CN; s++) acc += sh_M[d * CN + s] * sh_h[s][f];
        z += sh_mv[d] * fmaxf(acc, 0.f);
    }
    zsh[f] = z;
    __syncthreads();

    float t = gb2[f];
    for (int g = 0; g < CHID; g++) t += zsh[g] * W2[g * CHID + f];
    rsh[f] = fmaxf(t, 0.f);
    __syncthreads();

    if (f < CN) {
        float o = linb[f];
        for (int g = 0; g < CHID; g++) o += rsh[g] * linW[g * CN + f];
        out[(size_t)b * CN + f] = o;
    }
}

// --------------------------------- launch --------------------------------------
extern "C" void kernel_launch(void* const* d_in, const int* in_sizes, int n_in,
                              void* d_out, int out_size)
{
    (void)n_in; (void)out_size;
    const float* img   = (const float*)d_in[0];
    const float* wemb  = (const float*)d_in[1];
    const int*   eidx  = (const int*)  d_in[2];
    const float* Wqkv  = (const float*)d_in[3];
    const float* bqkv  = (const float*)d_in[4];
    const float* Wo    = (const float*)d_in[5];
    const float* bo    = (const float*)d_in[6];
    const float* ln1g  = (const float*)d_in[7];
    const float* ln1b  = (const float*)d_in[8];
    const float* ln2g  = (const float*)d_in[9];
    const float* ln2b  = (const float*)d_in[10];
    const float* W1    = (const float*)d_in[11];
    const float* b1    = (const float*)d_in[12];
    const float* W2f   = (const float*)d_in[13];
    const float* b2    = (const float*)d_in[14];
    const float* g1w   = (const float*)d_in[15];
    const float* g1b   = (const float*)d_in[16];
    const float* g2w   = (const float*)d_in[17];
    const float* g2b   = (const float*)d_in[18];
    const float* linw  = (const float*)d_in[19];
    const float* linb  = (const float*)d_in[20];
    float* out = (float*)d_out;
    const int E = in_sizes[2] / 2;

    float *A3, *Bn3, *S0, *wnm, *AvWo, *BvWo, *P, *projao, *x1, *hff, *ffo, *x2, *h1, *Mm, *mv;
    cudaGetSymbolAddress((void**)&A3,     d_A3);
    cudaGetSymbolAddress((void**)&Bn3,    d_Bn3);
    cudaGetSymbolAddress((void**)&S0,     d_S0);
    cudaGetSymbolAddress((void**)&wnm,    d_wnm);
    cudaGetSymbolAddress((void**)&AvWo,   d_AvWo);
    cudaGetSymbolAddress((void**)&BvWo,   d_BvWo);
    cudaGetSymbolAddress((void**)&P,      d_P);
    cudaGetSymbolAddress((void**)&projao, d_projao);
    cudaGetSymbolAddress((void**)&x1,     d_x1);
    cudaGetSymbolAddress((void**)&hff,    d_hff);
    cudaGetSymbolAddress((void**)&ffo,    d_ffo);
    cudaGetSymbolAddress((void**)&x2,     d_x2);
    cudaGetSymbolAddress((void**)&h1,     d_h1);
    cudaGetSymbolAddress((void**)&Mm,     d_Mmat);
    cudaGetSymbolAddress((void**)&mv,     d_mvec);

    const float scale = 1.0f / sqrtf((float)CD);

    // QKV rank-separation: qkv[b,n] = A3[b] + Bn3[n]
    run_gemm(true,  false, img,  Wqkv,        A3,  nullptr, CB, C3D, CIMG, CIMG, CD, C3D, 0, 0, 0, 0, 1.f, 1);
    small_nt_kernel<<<(C3D + 31) / 32, 256>>>(wemb, Wqkv + CIMG, Bn3, bqkv, C3D, CTXT, CTXT, CD, C3D, 1.f);

    // Score pieces (softmax-invariant terms dropped)
    run_gemm(true,  false, A3,            A3 + CD, S0,  nullptr, CB, CB, CD, C3D, C3D, CB, 0, 0, 0, 0, scale, 1);
    small_nt_kernel<<<(CB + 31) / 32, 256>>>(Bn3, A3 + CD, wnm, nullptr, CB, CD, C3D, C3D, CB, scale);

    // Fold out-projection into V
    run_gemm(true,  false, A3 + 2 * CD,  Wo, AvWo, nullptr, CB, CD, CD, C3D, CD, CD, 0, 0, 0, 0, 1.f, 1);
    small_nt_kernel<<<(CD + 31) / 32, 256>>>(Bn3 + 2 * CD, Wo, BvWo, bo, CD, CD, C3D, CD, CD, 1.f);

    // Softmax per (n,l) row
    softmax_kernel<<<dim3(CB, CN), 256>>>(S0, wnm, P);

    // projao[l,n,:] = P_n[l,:] @ AvWo + BvWo[n]   (batched over n)
    run_gemm(false, false, P, AvWo, projao, BvWo, CB, CD, CB, CB, CD, CN * CD,
             (long long)CB * CB, 0, CD, CD, 1.f, CN);

    // x1 = LN(node + projao)
    ln1_kernel<<<CT, 256>>>(img, wemb, projao, ln1g, ln1b, x1);

    // FFN
    run_gemm(false, true,  x1,  W1,  hff, b1, CT, CFF, CD,  CD,  CFF, CFF, 0, 0, 0, 0, 1.f, 1);
    run_gemm(false, false, hff, W2f, ffo, b2, CT, CD,  CFF, CFF, CD,  CD,  0, 0, 0, 0, 1.f, 1);

    // x2 = LN(x1 + ffn)
    ln2_kernel<<<CT, 256>>>(x1, ffo, ln2g, ln2b, x2);

    // GCN feature transform: h1 = x2 @ gcn1_w
    run_gemm(false, false, x2, g1w, h1, nullptr, CT, CHID, CD, CD, CHID, CHID, 0, 0, 0, 0, 1.f, 1);

    // Dense adjacency + fused tail
    gcn_prep_kernel<<<1, 256>>>(eidx, E, Mm, mv);
    gcn_final_kernel<<<CB, 128>>>(h1, Mm, mv, g1b, g2w, g2b, linw, linb, out);
}